// round 15
// baseline (speedup 1.0000x reference)
#include <cuda_runtime.h>
#include <cstdint>
#include <math.h>

#define NBLK2 128

__device__ float g_xg[16384ull * 3072];
__device__ float g_wt[1024 * 1024];
__device__ float g_wcomb[3072 * 1024];
__device__ float g_bcomb[3072];
__device__ float g_hfin[64 * 1024];
__device__ float g_ht[2][1024 * 64];      // transposed hidden ping-pong: [k][b]
__device__ unsigned g_cnt = 0, g_gen = 0;

// ---------------- f32x2 helpers ----------------
__device__ __forceinline__ uint64_t pack2(float lo, float hi) {
    uint64_t r;
    asm("mov.b64 %0, {%1, %2};" : "=l"(r) : "f"(lo), "f"(hi));
    return r;
}
__device__ __forceinline__ void unpack2(uint64_t v, float& lo, float& hi) {
    asm("mov.b64 {%0, %1}, %2;" : "=f"(lo), "=f"(hi) : "l"(v));
}
__device__ __forceinline__ uint64_t ffma2(uint64_t a, uint64_t b, uint64_t c) {
    uint64_t d;
    asm("fma.rn.f32x2 %0, %1, %2, %3;" : "=l"(d) : "l"(a), "l"(b), "l"(c));
    return d;
}

// ---------------- prep kernels ----------------
__global__ void transpose_k(const float* __restrict__ in, float* __restrict__ out) {
    __shared__ float t[32][33];
    int x = blockIdx.x * 32 + threadIdx.x, y = blockIdx.y * 32 + threadIdx.y;
    #pragma unroll
    for (int i = 0; i < 32; i += 8) t[threadIdx.y + i][threadIdx.x] = in[(size_t)(y + i) * 1024 + x];
    __syncthreads();
    int xo = blockIdx.y * 32 + threadIdx.x, yo = blockIdx.x * 32 + threadIdx.y;
    #pragma unroll
    for (int i = 0; i < 32; i += 8) out[(size_t)(yo + i) * 1024 + xo] = t[threadIdx.x][threadIdx.y + i];
}
__global__ void bcomb_k(const float* __restrict__ W, const float* __restrict__ b_in,
                        const float* __restrict__ b_ih, float* __restrict__ out) {
    int g = blockIdx.x * blockDim.x + threadIdx.x;
    if (g < 3072) {
        float s = b_ih[g];
        const float* row = W + (size_t)g * 1024;
        for (int h = 0; h < 1024; h++) s += row[h] * b_in[h];
        out[g] = s;
    }
}
__global__ void copy_k(const float* __restrict__ s, float* __restrict__ d, int n) {
    int i = blockIdx.x * blockDim.x + threadIdx.x;
    if (i < n) d[i] = s[i];
}

// =====================================================================
// SIMT fp32 NT GEMM via fma.rn.f32x2, ZERO-PACK + explicit frag
// double-buffering. 192x128 tile, BK=16, 384 threads (170-reg budget).
// A row-pairs direct LDS.128; B DUPLICATED in smem -> direct LDS.64.
// Inner loop: load k+1 frags into alternate buffer, FMA on current ->
// LDS->FMA distance = full iteration, no scoreboard stalls.
// =====================================================================
#define GEMM_SMEM ((2 * 16 * 200 + 2 * 16 * 260) * 4)   // 58880 bytes
#define ASX(b, k, r)  sm[((b) * 16 + (k)) * 200 + (r)]
#define BDX(b, k, c2) sm[6400 + ((b) * 16 + (k)) * 260 + (c2)]

__global__ __launch_bounds__(384, 1)
void gemm_f2_k(const float* __restrict__ A, const float* __restrict__ B,
               const float* __restrict__ bias, float* __restrict__ C,
               int M, int N, int K)
{
    extern __shared__ float sm[];
    const int tid = threadIdx.x, tx = tid & 15, ty = tid >> 4;   // ty 0..23
    const int mB = blockIdx.y * 192, nB = blockIdx.x * 128;

    uint64_t acc[4][8];
    #pragma unroll
    for (int i = 0; i < 4; i++)
        #pragma unroll
        for (int j = 0; j < 8; j++) acc[i][j] = 0ull;

    const int NKT = K >> 4;
    // A staging: 768 f4 (2/thread); B staging: 512 f4 (1/thread + extra for tid<128)
    int ar[2], ak[2];
    #pragma unroll
    for (int i = 0; i < 2; i++) {
        int id = tid + i * 384;
        ar[i] = id >> 2; ak[i] = (id & 3) << 2;
    }
    const int br = tid >> 2, bk = (tid & 3) << 2;
    const int br2 = (tid + 384) >> 2, bk2 = ((tid + 384) & 3) << 2;
    const bool hasB2 = (tid < 128);

    float4 ra[2], rb, rb2;
    #pragma unroll
    for (int i = 0; i < 2; i++)
        ra[i] = (mB + ar[i] < M) ? *reinterpret_cast<const float4*>(A + (size_t)(mB + ar[i]) * K + ak[i])
                                 : make_float4(0.f, 0.f, 0.f, 0.f);
    rb = *reinterpret_cast<const float4*>(B + (size_t)(nB + br) * K + bk);
    if (hasB2) rb2 = *reinterpret_cast<const float4*>(B + (size_t)(nB + br2) * K + bk2);

    #pragma unroll
    for (int i = 0; i < 2; i++) {
        const float* p = &ra[i].x;
        #pragma unroll
        for (int j = 0; j < 4; j++) ASX(0, ak[i] + j, ar[i]) = p[j];
    }
    {
        const float* p = &rb.x;
        #pragma unroll
        for (int j = 0; j < 4; j++) {
            BDX(0, bk + j, 2 * br) = p[j];
            BDX(0, bk + j, 2 * br + 1) = p[j];
        }
    }
    if (hasB2) {
        const float* p = &rb2.x;
        #pragma unroll
        for (int j = 0; j < 4; j++) {
            BDX(0, bk2 + j, 2 * br2) = p[j];
            BDX(0, bk2 + j, 2 * br2 + 1) = p[j];
        }
    }
    __syncthreads();

    uint64_t apf[2][4], bdf[2][8];
    #define LDFRAG(buf, bb, kk) do { \
        ulonglong2 t0_ = *reinterpret_cast<const ulonglong2*>(&ASX(bb, kk, ty * 8)); \
        ulonglong2 t1_ = *reinterpret_cast<const ulonglong2*>(&ASX(bb, kk, ty * 8 + 4)); \
        apf[buf][0] = t0_.x; apf[buf][1] = t0_.y; apf[buf][2] = t1_.x; apf[buf][3] = t1_.y; \
        _Pragma("unroll") \
        for (int j_ = 0; j_ < 8; j_++) \
            bdf[buf][j_] = *reinterpret_cast<const uint64_t*>(&BDX(bb, kk, 2 * (tx + 16 * j_))); \
    } while (0)

    for (int kt = 0; kt < NKT; kt++) {
        const int b = kt & 1;
        if (kt + 1 < NKT) {
            int k0 = (kt + 1) << 4;
            #pragma unroll
            for (int i = 0; i < 2; i++)
                ra[i] = (mB + ar[i] < M) ? *reinterpret_cast<const float4*>(A + (size_t)(mB + ar[i]) * K + k0 + ak[i])
                                         : make_float4(0.f, 0.f, 0.f, 0.f);
            rb = *reinterpret_cast<const float4*>(B + (size_t)(nB + br) * K + k0 + bk);
            if (hasB2) rb2 = *reinterpret_cast<const float4*>(B + (size_t)(nB + br2) * K + k0 + bk2);
        }
        LDFRAG(0, b, 0);
        #pragma unroll
        for (int k = 0; k < 16; k++) {
            const int cb = k & 1;
            if (k < 15) LDFRAG(cb ^ 1, b, k + 1);
            #pragma unroll
            for (int i = 0; i < 4; i++)
                #pragma unroll
                for (int j = 0; j < 8; j++) acc[i][j] = ffma2(apf[cb][i], bdf[cb][j], acc[i][j]);
        }
        if (kt + 1 < NKT) {
            int nb = b ^ 1;
            #pragma unroll
            for (int i = 0; i < 2; i++) {
                const float* p = &ra[i].x;
                #pragma unroll
                for (int j = 0; j < 4; j++) ASX(nb, ak[i] + j, ar[i]) = p[j];
            }
            {
                const float* p = &rb.x;
                #pragma unroll
                for (int j = 0; j < 4; j++) {
                    BDX(nb, bk + j, 2 * br) = p[j];
                    BDX(nb, bk + j, 2 * br + 1) = p[j];
                }
            }
            if (hasB2) {
                const float* p = &rb2.x;
                #pragma unroll
                for (int j = 0; j < 4; j++) {
                    BDX(nb, bk2 + j, 2 * br2) = p[j];
                    BDX(nb, bk2 + j, 2 * br2 + 1) = p[j];
                }
            }
            __syncthreads();
        }
    }

    // epilogue: acc[rp][j] = rows (mB+ty*8+2rp, +1), col tx+16j
    #pragma unroll
    for (int rp = 0; rp < 4; rp++) {
        int r0 = mB + ty * 8 + 2 * rp;
        float* c0 = C + (size_t)r0 * N + nB;
        float* c1 = C + (size_t)(r0 + 1) * N + nB;
        #pragma unroll
        for (int j = 0; j < 8; j++) {
            int col = tx + 16 * j;
            float lo, hi;
            unpack2(acc[rp][j], lo, hi);
            float bv = bias ? bias[nB + col] : 0.f;
            if (r0 < M)     c0[col] = lo + bv;
            if (r0 + 1 < M) c1[col] = hi + bv;
        }
    }
}

// =====================================================================
// Persistent SIMT GRU recurrence — R14 version, unchanged.
// =====================================================================
#define GRU_SMEM (1024 * 24 * 4 + 16 * 64 * 26 * 4)   // 204800

__device__ __forceinline__ void gridbar() {
    __syncthreads();
    if (threadIdx.x == 0) {
        __threadfence();
        unsigned gen = *((volatile unsigned*)&g_gen);
        if (atomicAdd(&g_cnt, 1u) == NBLK2 - 1u) {
            atomicExch(&g_cnt, 0u);
            __threadfence();
            atomicAdd(&g_gen, 1u);
        } else {
            while (*((volatile unsigned*)&g_gen) == gen) { }
        }
        __threadfence();
    }
    __syncthreads();
}

__global__ __launch_bounds__(512, 1)
void gru_f2_k(const float* __restrict__ xg, const float* __restrict__ W_hh,
              const float* __restrict__ b_hh, const float* __restrict__ hidden,
              float* __restrict__ hfin)
{
    extern __shared__ float sm[];
    float* Wt = sm;                 // [1024][24] natural (row-pairs adjacent)
    float* shg = sm + 24576;        // [16][64][26]
    __shared__ float sbh[24];

    const int tid = threadIdx.x;
    const int warp = tid >> 5, lane = tid & 31;
    const int k0 = warp << 6;                // warp's unique 64-k slice
    const int j0 = blockIdx.x * 8;
    const int bg = tid >> 3, ug = tid & 7;   // gates mapping: 64 x 8

    // stage Wt: Wt[k][r] = W_hh[(r/8)*1024 + j0 + (r%8)][k]
    #pragma unroll 1
    for (int it = 0; it < 12; it++) {
        int f4 = tid + it * 512;          // 0..6143
        int r = f4 >> 8;                  // 0..23
        int kq = (f4 & 255) << 2;         // 0..1020
        int grow = (r >> 3) * 1024 + j0 + (r & 7);
        float4 v = *reinterpret_cast<const float4*>(W_hh + (size_t)grow * 1024 + kq);
        Wt[(kq + 0) * 24 + r] = v.x;
        Wt[(kq + 1) * 24 + r] = v.y;
        Wt[(kq + 2) * 24 + r] = v.z;
        Wt[(kq + 3) * 24 + r] = v.w;
    }
    if (tid < 24) sbh[tid] = b_hh[(tid >> 3) * 1024 + j0 + (tid & 7)];

    // init transposed h slice for this block's 8 units (512 = 8*64 exactly)
    g_ht[0][(j0 + ug) * 64 + bg] = hidden[(size_t)bg * 1024 + j0 + ug];
    __syncthreads();
    gridbar();

    for (int t = 0; t < 256; t++) {
        const float* hs = g_ht[t & 1];
        float* hnx = g_ht[(t + 1) & 1];

        // prefetch gates operands (independent of dot loop)
        float xrv, xzv, xnv, hold;
        {
            const float* xp = xg + (size_t)(bg * 256 + t) * 3072 + j0 + ug;
            xrv = xp[0]; xzv = xp[1024]; xnv = xp[2048];
            hold = hs[(j0 + ug) * 64 + bg];
        }

        // dot: warp's unique 64-k slice, ALL 24 rows, batch pair (2lane,2lane+1)
        uint64_t acc[12][2];
        #pragma unroll
        for (int p = 0; p < 12; p++) { acc[p][0] = 0ull; acc[p][1] = 0ull; }

        const float* hp = hs + 2 * lane;

        // 8-deep double-buffered register prefetch of the h stream
        float2 hb[2][8];
        #pragma unroll
        for (int i = 0; i < 8; i++)
            hb[0][i] = *reinterpret_cast<const float2*>(hp + (size_t)(k0 + i) * 64);

        #pragma unroll
        for (int c = 0; c < 8; c++) {
            const int cb = c & 1, nb = cb ^ 1;
            if (c < 7) {
                #pragma unroll
                for (int i = 0; i < 8; i++)
                    hb[nb][i] = *reinterpret_cast<const float2*>(hp + (size_t)(k0 + (c + 1) * 8 + i) * 64);
            }
            #pragma unroll
            for (int i = 0; i < 8; i++) {
                const int k = k0 + c * 8 + i;
                float2 hv = hb[cb][i];
                uint64_t d0 = pack2(hv.x, hv.x);
                uint64_t d1 = pack2(hv.y, hv.y);
                const float* wk = Wt + k * 24;
                ulonglong2 wA = *reinterpret_cast<const ulonglong2*>(wk);
                ulonglong2 wB = *reinterpret_cast<const ulonglong2*>(wk + 4);
                ulonglong2 wC = *reinterpret_cast<const ulonglong2*>(wk + 8);
                ulonglong2 wD = *reinterpret_cast<const ulonglong2*>(wk + 12);
                ulonglong2 wE = *reinterpret_cast<const ulonglong2*>(wk + 16);
                ulonglong2 wF = *reinterpret_cast<const ulonglong2*>(wk + 20);
                acc[0][0]  = ffma2(d0, wA.x, acc[0][0]);   acc[0][1]  = ffma2(d1, wA.x, acc[0][1]);
                acc[1][0]  = ffma2(d0, wA.y, acc[1][0]);   acc[1][1]  = ffma2(d1, wA.y, acc[1][1]);
                acc[2][0]  = ffma2(d0, wB.x, acc[2][0]);   acc[2][1]  = ffma2(d1, wB.x, acc[2][1]);
                acc[3][0]  = ffma2(d0, wB.y, acc[3][0]);   acc[3][1]  = ffma2(d1, wB.y, acc[3][1]);
                acc[4][0]  = ffma2(d0, wC.x, acc[4][0]);   acc[4][1]  = ffma2(d1, wC.x, acc[4][1]);
                acc[5][0]  = ffma2(d0, wC.y, acc[5][0]);   acc[5][1]  = ffma2(d1, wC.y, acc[5][1]);
                acc[6][0]  = ffma2(d0, wD.x, acc[6][0]);   acc[6][1]  = ffma2(d1, wD.x, acc[6][1]);
                acc[7][0]  = ffma2(d0, wD.y, acc[7][0]);   acc[7][1]  = ffma2(d1, wD.y, acc[7][1]);
                acc[8][0]  = ffma2(d0, wE.x, acc[8][0]);   acc[8][1]  = ffma2(d1, wE.x, acc[8][1]);
                acc[9][0]  = ffma2(d0, wE.y, acc[9][0]);   acc[9][1]  = ffma2(d1, wE.y, acc[9][1]);
                acc[10][0] = ffma2(d0, wF.x, acc[10][0]);  acc[10][1] = ffma2(d1, wF.x, acc[10][1]);
                acc[11][0] = ffma2(d0, wF.y, acc[11][0]);  acc[11][1] = ffma2(d1, wF.y, acc[11][1]);
            }
        }
        // store partials: acc[p][i] = (row2p, row2p+1) for batch 2lane+i
        {
            float* p0 = shg + (size_t)(warp * 64 + 2 * lane) * 26;
            float* p1 = p0 + 26;
            #pragma unroll
            for (int p = 0; p < 12; p++) {
                *reinterpret_cast<uint64_t*>(p0 + 2 * p) = acc[p][0];
                *reinterpret_cast<uint64_t*>(p1 + 2 * p) = acc[p][1];
            }
        }
        __syncthreads();

        // reduce 16 k-slices + fused gates: thread = (bg, ug)
        {
            float hr = 0.f, hz = 0.f, hn2 = 0.f;
            #pragma unroll
            for (int s = 0; s < 16; s++) {
                const float* base = shg + (size_t)(s * 64 + bg) * 26;
                hr  += base[ug];
                hz  += base[8 + ug];
                hn2 += base[16 + ug];
            }
            float r = 1.f / (1.f + expf(-(xrv + hr + sbh[ug])));
            float z = 1.f / (1.f + expf(-(xzv + hz + sbh[8 + ug])));
            float n = tanhf(xnv + r * (hn2 + sbh[16 + ug]));
            float hnew = (1.f - z) * n + z * hold;
            hnx[(j0 + ug) * 64 + bg] = hnew;
            if (t == 255) hfin[(size_t)bg * 1024 + j0 + ug] = hnew;
        }
        gridbar();
    }
}

// =====================================================================
// launch
// =====================================================================
extern "C" void kernel_launch(void* const* d_in, const int* in_sizes, int n_in,
                              void* d_out, int out_size)
{
    const float* inp    = (const float*)d_in[0];
    const float* hidden = (const float*)d_in[1];
    const float* W_in   = (const float*)d_in[2];
    const float* b_in   = (const float*)d_in[3];
    const float* W_ih   = (const float*)d_in[4];
    const float* b_ih   = (const float*)d_in[5];
    const float* W_hh   = (const float*)d_in[6];
    const float* b_hh   = (const float*)d_in[7];
    const float* W_out  = (const float*)d_in[8];
    const float* b_out  = (const float*)d_in[9];
    float* out = (float*)d_out;

    cudaFuncSetAttribute(gemm_f2_k, cudaFuncAttributeMaxDynamicSharedMemorySize, GEMM_SMEM);
    cudaFuncSetAttribute(gru_f2_k, cudaFuncAttributeMaxDynamicSharedMemorySize, GRU_SMEM);

    // W_in^T
    transpose_k<<<dim3(32, 32), dim3(32, 8)>>>(W_in, g_wt);
    // b_comb = W_ih @ b_in + b_ih
    bcomb_k<<<12, 256>>>(W_ih, b_in, b_ih, g_bcomb);
    // W_comb = W_ih @ W_in          (M=3072, N=1024, K=1024) — 3072/192=16
    gemm_f2_k<<<dim3(8, 16), 384, GEMM_SMEM>>>(W_ih, g_wt, nullptr, g_wcomb, 3072, 1024, 1024);
    // x_gates = inp @ W_comb^T + b  (M=16384, N=3072, K=1024) — ceil(16384/192)=86
    gemm_f2_k<<<dim3(24, 86), 384, GEMM_SMEM>>>(inp, g_wcomb, g_bcomb, g_xg, 16384, 3072, 1024);
    // recurrence (persistent)
    gru_f2_k<<<NBLK2, 512, GRU_SMEM>>>(g_xg, W_hh, b_hh, hidden, g_hfin);
    // out_last = h_T @ W_out^T + b  (M=64, N=1024, K=1024)
    gemm_f2_k<<<dim3(8, 1), 384, GEMM_SMEM>>>(g_hfin, W_out, b_out, out, 64, 1024, 1024);
    // hidden_out = h_T
    copy_k<<<256, 256>>>(g_hfin, out + 65536, 65536);
}

// round 16
// speedup vs baseline: 1.1016x; 1.1016x over previous
#include <cuda_runtime.h>
#include <cstdint>
#include <math.h>

#define NBLK2 128

__device__ float g_xg[16384ull * 3072];
__device__ float g_wt[1024 * 1024];
__device__ float g_wcomb[3072 * 1024];
__device__ float g_bcomb[3072];
__device__ float g_hfin[64 * 1024];
__device__ float g_ht[2][1024 * 64];      // transposed hidden ping-pong: [k][b]
__device__ unsigned g_cnt8[8 * 32];        // 8 group counters, 128B apart
__device__ unsigned g_root = 0;
__device__ unsigned g_gen = 0;

// ---------------- f32x2 helpers ----------------
__device__ __forceinline__ uint64_t pack2(float lo, float hi) {
    uint64_t r;
    asm("mov.b64 %0, {%1, %2};" : "=l"(r) : "f"(lo), "f"(hi));
    return r;
}
__device__ __forceinline__ void unpack2(uint64_t v, float& lo, float& hi) {
    asm("mov.b64 {%0, %1}, %2;" : "=f"(lo), "=f"(hi) : "l"(v));
}
__device__ __forceinline__ uint64_t ffma2(uint64_t a, uint64_t b, uint64_t c) {
    uint64_t d;
    asm("fma.rn.f32x2 %0, %1, %2, %3;" : "=l"(d) : "l"(a), "l"(b), "l"(c));
    return d;
}

// ---------------- prep kernels ----------------
__global__ void transpose_k(const float* __restrict__ in, float* __restrict__ out) {
    __shared__ float t[32][33];
    int x = blockIdx.x * 32 + threadIdx.x, y = blockIdx.y * 32 + threadIdx.y;
    #pragma unroll
    for (int i = 0; i < 32; i += 8) t[threadIdx.y + i][threadIdx.x] = in[(size_t)(y + i) * 1024 + x];
    __syncthreads();
    int xo = blockIdx.y * 32 + threadIdx.x, yo = blockIdx.x * 32 + threadIdx.y;
    #pragma unroll
    for (int i = 0; i < 32; i += 8) out[(size_t)(yo + i) * 1024 + xo] = t[threadIdx.x][threadIdx.y + i];
}
__global__ void bcomb_k(const float* __restrict__ W, const float* __restrict__ b_in,
                        const float* __restrict__ b_ih, float* __restrict__ out) {
    int g = blockIdx.x * blockDim.x + threadIdx.x;
    if (g < 3072) {
        float s = b_ih[g];
        const float* row = W + (size_t)g * 1024;
        for (int h = 0; h < 1024; h++) s += row[h] * b_in[h];
        out[g] = s;
    }
}
__global__ void copy_k(const float* __restrict__ s, float* __restrict__ d, int n) {
    int i = blockIdx.x * blockDim.x + threadIdx.x;
    if (i < n) d[i] = s[i];
}

// =====================================================================
// SIMT fp32 NT GEMM via fma.rn.f32x2, ZERO-PACK (R12/R14 version — local
// optimum, DO NOT PERTURB). 256x128 tile, BK=16, 512 threads.
// =====================================================================
#define GEMM_SMEM (2 * 16 * 260 * 2 * 4)   // As + Bd, 66560 bytes
#define ASX(b, k, r)  sm[((b) * 16 + (k)) * 260 + (r)]
#define BDX(b, k, c2) sm[8320 + ((b) * 16 + (k)) * 260 + (c2)]

__global__ __launch_bounds__(512, 1)
void gemm_f2_k(const float* __restrict__ A, const float* __restrict__ B,
               const float* __restrict__ bias, float* __restrict__ C,
               int M, int N, int K)
{
    extern __shared__ float sm[];
    const int tid = threadIdx.x, tx = tid & 15, ty = tid >> 4;   // ty 0..31
    const int mB = blockIdx.y * 256, nB = blockIdx.x * 128;

    uint64_t acc[4][8];
    #pragma unroll
    for (int i = 0; i < 4; i++)
        #pragma unroll
        for (int j = 0; j < 8; j++) acc[i][j] = 0ull;

    const int NKT = K >> 4;
    int ar[2], ak[2];
    #pragma unroll
    for (int i = 0; i < 2; i++) {
        int id = tid + i * 512;
        ar[i] = id >> 2; ak[i] = (id & 3) << 2;
    }
    const int br = tid >> 2, bk = (tid & 3) << 2;

    float4 ra[2], rb;
    #pragma unroll
    for (int i = 0; i < 2; i++)
        ra[i] = (mB + ar[i] < M) ? *reinterpret_cast<const float4*>(A + (size_t)(mB + ar[i]) * K + ak[i])
                                 : make_float4(0.f, 0.f, 0.f, 0.f);
    rb = *reinterpret_cast<const float4*>(B + (size_t)(nB + br) * K + bk);

    #pragma unroll
    for (int i = 0; i < 2; i++) {
        const float* p = &ra[i].x;
        #pragma unroll
        for (int j = 0; j < 4; j++) ASX(0, ak[i] + j, ar[i]) = p[j];
    }
    {
        const float* p = &rb.x;
        #pragma unroll
        for (int j = 0; j < 4; j++) {
            BDX(0, bk + j, 2 * br) = p[j];
            BDX(0, bk + j, 2 * br + 1) = p[j];
        }
    }
    __syncthreads();

    for (int kt = 0; kt < NKT; kt++) {
        const int b = kt & 1;
        if (kt + 1 < NKT) {
            int k0 = (kt + 1) << 4;
            #pragma unroll
            for (int i = 0; i < 2; i++)
                ra[i] = (mB + ar[i] < M) ? *reinterpret_cast<const float4*>(A + (size_t)(mB + ar[i]) * K + k0 + ak[i])
                                         : make_float4(0.f, 0.f, 0.f, 0.f);
            rb = *reinterpret_cast<const float4*>(B + (size_t)(nB + br) * K + k0 + bk);
        }
        #pragma unroll
        for (int k = 0; k < 16; k++) {
            uint64_t ap[4];
            ap[0] = *reinterpret_cast<const uint64_t*>(&ASX(b, k, ty * 4));
            ap[1] = *reinterpret_cast<const uint64_t*>(&ASX(b, k, ty * 4 + 2));
            ap[2] = *reinterpret_cast<const uint64_t*>(&ASX(b, k, 128 + ty * 4));
            ap[3] = *reinterpret_cast<const uint64_t*>(&ASX(b, k, 128 + ty * 4 + 2));
            uint64_t bd[8];
            #pragma unroll
            for (int j = 0; j < 8; j++)
                bd[j] = *reinterpret_cast<const uint64_t*>(&BDX(b, k, 2 * (tx + 16 * j)));
            #pragma unroll
            for (int i = 0; i < 4; i++)
                #pragma unroll
                for (int j = 0; j < 8; j++) acc[i][j] = ffma2(ap[i], bd[j], acc[i][j]);
        }
        if (kt + 1 < NKT) {
            int nb = b ^ 1;
            #pragma unroll
            for (int i = 0; i < 2; i++) {
                const float* p = &ra[i].x;
                #pragma unroll
                for (int j = 0; j < 4; j++) ASX(nb, ak[i] + j, ar[i]) = p[j];
            }
            {
                const float* p = &rb.x;
                #pragma unroll
                for (int j = 0; j < 4; j++) {
                    BDX(nb, bk + j, 2 * br) = p[j];
                    BDX(nb, bk + j, 2 * br + 1) = p[j];
                }
            }
            __syncthreads();
        }
    }

    // epilogue: acc[rp][j] = rows (r0, r0+1), col tx+16j
    #pragma unroll
    for (int rp = 0; rp < 4; rp++) {
        int r0 = mB + ((rp < 2) ? ty * 4 + 2 * rp : 128 + ty * 4 + 2 * (rp - 2));
        float* c0 = C + (size_t)r0 * N + nB;
        float* c1 = C + (size_t)(r0 + 1) * N + nB;
        #pragma unroll
        for (int j = 0; j < 8; j++) {
            int col = tx + 16 * j;
            float lo, hi;
            unpack2(acc[rp][j], lo, hi);
            float bv = bias ? bias[nB + col] : 0.f;
            if (r0 < M)     c0[col] = lo + bv;
            if (r0 + 1 < M) c1[col] = hi + bv;
        }
    }
}

// =====================================================================
// Persistent SIMT GRU recurrence — R14 version + HIERARCHICAL grid
// barrier: 8 group counters (16 blocks each, separate 128B lines) +
// root counter. Same-address atomic serialization (128 x ~27cy) drops
// to ~16 x 27 in parallel groups + 8 at root.
// =====================================================================
#define GRU_SMEM (1024 * 24 * 4 + 16 * 64 * 26 * 4)   // 204800

__device__ __forceinline__ void gridbar(int bx) {
    __syncthreads();
    if (threadIdx.x == 0) {
        __threadfence();
        unsigned gen = *((volatile unsigned*)&g_gen);
        int grp = bx & 7;
        if (atomicAdd(&g_cnt8[grp * 32], 1u) == 15u) {          // group leader (16/group)
            if (atomicAdd(&g_root, 1u) == 7u) {                 // last group
                atomicExch(&g_root, 0u);
                #pragma unroll
                for (int i = 0; i < 8; i++) atomicExch(&g_cnt8[i * 32], 0u);
                __threadfence();
                atomicAdd(&g_gen, 1u);                          // release
            }
        }
        while (*((volatile unsigned*)&g_gen) == gen) { }
        __threadfence();
    }
    __syncthreads();
}

__global__ __launch_bounds__(512, 1)
void gru_f2_k(const float* __restrict__ xg, const float* __restrict__ W_hh,
              const float* __restrict__ b_hh, const float* __restrict__ hidden,
              float* __restrict__ hfin)
{
    extern __shared__ float sm[];
    float* Wt = sm;                 // [1024][24] natural (row-pairs adjacent)
    float* shg = sm + 24576;        // [16][64][26]
    __shared__ float sbh[24];

    const int tid = threadIdx.x;
    const int warp = tid >> 5, lane = tid & 31;
    const int k0 = warp << 6;                // warp's unique 64-k slice
    const int j0 = blockIdx.x * 8;
    const int bg = tid >> 3, ug = tid & 7;   // gates mapping: 64 x 8

    // stage Wt: Wt[k][r] = W_hh[(r/8)*1024 + j0 + (r%8)][k]
    #pragma unroll 1
    for (int it = 0; it < 12; it++) {
        int f4 = tid + it * 512;          // 0..6143
        int r = f4 >> 8;                  // 0..23
        int kq = (f4 & 255) << 2;         // 0..1020
        int grow = (r >> 3) * 1024 + j0 + (r & 7);
        float4 v = *reinterpret_cast<const float4*>(W_hh + (size_t)grow * 1024 + kq);
        Wt[(kq + 0) * 24 + r] = v.x;
        Wt[(kq + 1) * 24 + r] = v.y;
        Wt[(kq + 2) * 24 + r] = v.z;
        Wt[(kq + 3) * 24 + r] = v.w;
    }
    if (tid < 24) sbh[tid] = b_hh[(tid >> 3) * 1024 + j0 + (tid & 7)];

    // init transposed h slice for this block's 8 units (512 = 8*64 exactly)
    g_ht[0][(j0 + ug) * 64 + bg] = hidden[(size_t)bg * 1024 + j0 + ug];
    __syncthreads();
    gridbar(blockIdx.x);

    for (int t = 0; t < 256; t++) {
        const float* hs = g_ht[t & 1];
        float* hnx = g_ht[(t + 1) & 1];

        // prefetch gates operands (independent of dot loop)
        float xrv, xzv, xnv, hold;
        {
            const float* xp = xg + (size_t)(bg * 256 + t) * 3072 + j0 + ug;
            xrv = xp[0]; xzv = xp[1024]; xnv = xp[2048];
            hold = hs[(j0 + ug) * 64 + bg];
        }

        // dot: warp's unique 64-k slice, ALL 24 rows, batch pair (2lane,2lane+1)
        uint64_t acc[12][2];
        #pragma unroll
        for (int p = 0; p < 12; p++) { acc[p][0] = 0ull; acc[p][1] = 0ull; }

        const float* hp = hs + 2 * lane;

        // 8-deep double-buffered register prefetch of the h stream
        float2 hb[2][8];
        #pragma unroll
        for (int i = 0; i < 8; i++)
            hb[0][i] = *reinterpret_cast<const float2*>(hp + (size_t)(k0 + i) * 64);

        #pragma unroll
        for (int c = 0; c < 8; c++) {
            const int cb = c & 1, nb = cb ^ 1;
            if (c < 7) {
                #pragma unroll
                for (int i = 0; i < 8; i++)
                    hb[nb][i] = *reinterpret_cast<const float2*>(hp + (size_t)(k0 + (c + 1) * 8 + i) * 64);
            }
            #pragma unroll
            for (int i = 0; i < 8; i++) {
                const int k = k0 + c * 8 + i;
                float2 hv = hb[cb][i];
                uint64_t d0 = pack2(hv.x, hv.x);
                uint64_t d1 = pack2(hv.y, hv.y);
                const float* wk = Wt + k * 24;
                ulonglong2 wA = *reinterpret_cast<const ulonglong2*>(wk);
                ulonglong2 wB = *reinterpret_cast<const ulonglong2*>(wk + 4);
                ulonglong2 wC = *reinterpret_cast<const ulonglong2*>(wk + 8);
                ulonglong2 wD = *reinterpret_cast<const ulonglong2*>(wk + 12);
                ulonglong2 wE = *reinterpret_cast<const ulonglong2*>(wk + 16);
                ulonglong2 wF = *reinterpret_cast<const ulonglong2*>(wk + 20);
                acc[0][0]  = ffma2(d0, wA.x, acc[0][0]);   acc[0][1]  = ffma2(d1, wA.x, acc[0][1]);
                acc[1][0]  = ffma2(d0, wA.y, acc[1][0]);   acc[1][1]  = ffma2(d1, wA.y, acc[1][1]);
                acc[2][0]  = ffma2(d0, wB.x, acc[2][0]);   acc[2][1]  = ffma2(d1, wB.x, acc[2][1]);
                acc[3][0]  = ffma2(d0, wB.y, acc[3][0]);   acc[3][1]  = ffma2(d1, wB.y, acc[3][1]);
                acc[4][0]  = ffma2(d0, wC.x, acc[4][0]);   acc[4][1]  = ffma2(d1, wC.x, acc[4][1]);
                acc[5][0]  = ffma2(d0, wC.y, acc[5][0]);   acc[5][1]  = ffma2(d1, wC.y, acc[5][1]);
                acc[6][0]  = ffma2(d0, wD.x, acc[6][0]);   acc[6][1]  = ffma2(d1, wD.x, acc[6][1]);
                acc[7][0]  = ffma2(d0, wD.y, acc[7][0]);   acc[7][1]  = ffma2(d1, wD.y, acc[7][1]);
                acc[8][0]  = ffma2(d0, wE.x, acc[8][0]);   acc[8][1]  = ffma2(d1, wE.x, acc[8][1]);
                acc[9][0]  = ffma2(d0, wE.y, acc[9][0]);   acc[9][1]  = ffma2(d1, wE.y, acc[9][1]);
                acc[10][0] = ffma2(d0, wF.x, acc[10][0]);  acc[10][1] = ffma2(d1, wF.x, acc[10][1]);
                acc[11][0] = ffma2(d0, wF.y, acc[11][0]);  acc[11][1] = ffma2(d1, wF.y, acc[11][1]);
            }
        }
        // store partials: acc[p][i] = (row2p, row2p+1) for batch 2lane+i
        {
            float* p0 = shg + (size_t)(warp * 64 + 2 * lane) * 26;
            float* p1 = p0 + 26;
            #pragma unroll
            for (int p = 0; p < 12; p++) {
                *reinterpret_cast<uint64_t*>(p0 + 2 * p) = acc[p][0];
                *reinterpret_cast<uint64_t*>(p1 + 2 * p) = acc[p][1];
            }
        }
        __syncthreads();

        // reduce 16 k-slices + fused gates: thread = (bg, ug)
        {
            float hr = 0.f, hz = 0.f, hn2 = 0.f;
            #pragma unroll
            for (int s = 0; s < 16; s++) {
                const float* base = shg + (size_t)(s * 64 + bg) * 26;
                hr  += base[ug];
                hz  += base[8 + ug];
                hn2 += base[16 + ug];
            }
            float r = 1.f / (1.f + expf(-(xrv + hr + sbh[ug])));
            float z = 1.f / (1.f + expf(-(xzv + hz + sbh[8 + ug])));
            float n = tanhf(xnv + r * (hn2 + sbh[16 + ug]));
            float hnew = (1.f - z) * n + z * hold;
            hnx[(j0 + ug) * 64 + bg] = hnew;
            if (t == 255) hfin[(size_t)bg * 1024 + j0 + ug] = hnew;
        }
        gridbar(blockIdx.x);
    }
}

// =====================================================================
// launch
// =====================================================================
extern "C" void kernel_launch(void* const* d_in, const int* in_sizes, int n_in,
                              void* d_out, int out_size)
{
    const float* inp    = (const float*)d_in[0];
    const float* hidden = (const float*)d_in[1];
    const float* W_in   = (const float*)d_in[2];
    const float* b_in   = (const float*)d_in[3];
    const float* W_ih   = (const float*)d_in[4];
    const float* b_ih   = (const float*)d_in[5];
    const float* W_hh   = (const float*)d_in[6];
    const float* b_hh   = (const float*)d_in[7];
    const float* W_out  = (const float*)d_in[8];
    const float* b_out  = (const float*)d_in[9];
    float* out = (float*)d_out;

    cudaFuncSetAttribute(gemm_f2_k, cudaFuncAttributeMaxDynamicSharedMemorySize, GEMM_SMEM);
    cudaFuncSetAttribute(gru_f2_k, cudaFuncAttributeMaxDynamicSharedMemorySize, GRU_SMEM);

    // W_in^T
    transpose_k<<<dim3(32, 32), dim3(32, 8)>>>(W_in, g_wt);
    // b_comb = W_ih @ b_in + b_ih
    bcomb_k<<<12, 256>>>(W_ih, b_in, b_ih, g_bcomb);
    // W_comb = W_ih @ W_in          (M=3072, N=1024, K=1024)
    gemm_f2_k<<<dim3(8, 12), 512, GEMM_SMEM>>>(W_ih, g_wt, nullptr, g_wcomb, 3072, 1024, 1024);
    // x_gates = inp @ W_comb^T + b  (M=16384, N=3072, K=1024)
    gemm_f2_k<<<dim3(24, 64), 512, GEMM_SMEM>>>(inp, g_wcomb, g_bcomb, g_xg, 16384, 3072, 1024);
    // recurrence (persistent)
    gru_f2_k<<<NBLK2, 512, GRU_SMEM>>>(g_xg, W_hh, b_hh, hidden, g_hfin);
    // out_last = h_T @ W_out^T + b  (M=64, N=1024, K=1024)
    gemm_f2_k<<<dim3(8, 1), 512, GEMM_SMEM>>>(g_hfin, W_out, b_out, out, 64, 1024, 1024);
    // hidden_out = h_T
    copy_k<<<256, 256>>>(g_hfin, out + 65536, 65536);
}